// round 13
// baseline (speedup 1.0000x reference)
#include <cuda_runtime.h>
#include <cuda_bf16.h>
#include <math.h>
#include <float.h>
#include <stdint.h>

// Problem constants (shapes fixed by the dataset)
#define N_ROWS 16384   // B*T = 8*2048
#define DDIM   512
#define KC     4096

// Scratch (device globals -- no allocation allowed)
__device__ float g_scores[(size_t)N_ROWS * KC];   // 256 MB (approx scores)
__device__ float g_c2[KC];
__device__ float g_rowerr[N_ROWS];
__device__ __nv_bfloat16 g_xb[(size_t)N_ROWS * DDIM];   // 16 MB
__device__ __nv_bfloat16 g_cbb[(size_t)KC * DDIM];      // 4 MB

#define SHORTCAP 160
#define MARGIN   0.5f

__device__ int   g_scnt[N_ROWS];                       // shortlist sizes
__device__ int   g_slist[(size_t)N_ROWS * SHORTCAP];   // shortlist indices

// ===========================================================================
// fp32 -> bf16 conversion for x and codebook
// ===========================================================================
__global__ void conv_kernel(const float* __restrict__ x, const float* __restrict__ cb) {
    size_t i = (size_t)blockIdx.x * blockDim.x + threadIdx.x;
    if (i < (size_t)N_ROWS * DDIM) g_xb[i]  = __float2bfloat16(x[i]);
    if (i < (size_t)KC * DDIM)     g_cbb[i] = __float2bfloat16(cb[i]);
}

// ---------------------------------------------------------------------------
// ||c_k||^2  (f32, for epilogue + rescore + tie simulation) -- R5-identical
// ---------------------------------------------------------------------------
__global__ void c2_kernel(const float* __restrict__ cb) {
    int k = blockIdx.x;
    const float* row = cb + (size_t)k * DDIM;
    float s = 0.f;
    for (int d = threadIdx.x; d < DDIM; d += 128) {
        float v = row[d];
        s += v * v;
    }
    __shared__ float sm[128];
    sm[threadIdx.x] = s;
    __syncthreads();
    for (int st = 64; st > 0; st >>= 1) {
        if (threadIdx.x < st) sm[threadIdx.x] += sm[threadIdx.x + st];
        __syncthreads();
    }
    if (threadIdx.x == 0) g_c2[k] = sm[0];
}

// ===========================================================================
// bf16 mma.sync GEMM (baseline-PTX HMMA; tcgen05 unavailable via compute_103).
// SELECTION ONLY: approx S[n,k] = 2*dot_bf16(x_n, c_k) - c2[k]
// Arithmetic unchanged; launch_bounds(256,2) for 2 CTAs/SM latency hiding.
// ===========================================================================
#define BKC 32
#define PAD 40

__device__ __forceinline__ uint32_t smem_u32(const void* p) {
    uint32_t a;
    asm("{ .reg .u64 t; cvta.to.shared.u64 t, %1; cvt.u32.u64 %0, t; }"
        : "=r"(a) : "l"(p));
    return a;
}
__device__ __forceinline__ void cp_async16(uint32_t dst, const void* src) {
    asm volatile("cp.async.cg.shared.global [%0], [%1], 16;"
                 :: "r"(dst), "l"(src));
}
__device__ __forceinline__ void cp_commit() {
    asm volatile("cp.async.commit_group;");
}
template <int N>
__device__ __forceinline__ void cp_wait() {
    asm volatile("cp.async.wait_group %0;" :: "n"(N));
}
__device__ __forceinline__ void ldsm_x4(uint32_t& a0, uint32_t& a1,
                                        uint32_t& a2, uint32_t& a3, uint32_t addr) {
    asm volatile("ldmatrix.sync.aligned.m8n8.x4.shared.b16 {%0,%1,%2,%3}, [%4];"
                 : "=r"(a0), "=r"(a1), "=r"(a2), "=r"(a3) : "r"(addr));
}
__device__ __forceinline__ void ldsm_x2(uint32_t& b0, uint32_t& b1, uint32_t addr) {
    asm volatile("ldmatrix.sync.aligned.m8n8.x2.shared.b16 {%0,%1}, [%2];"
                 : "=r"(b0), "=r"(b1) : "r"(addr));
}
__device__ __forceinline__ void mma_bf16(float& d0, float& d1, float& d2, float& d3,
                                         uint32_t a0, uint32_t a1, uint32_t a2, uint32_t a3,
                                         uint32_t b0, uint32_t b1) {
    asm volatile("mma.sync.aligned.m16n8k16.row.col.f32.bf16.bf16.f32 "
                 "{%0,%1,%2,%3}, {%4,%5,%6,%7}, {%8,%9}, {%0,%1,%2,%3};"
                 : "+f"(d0), "+f"(d1), "+f"(d2), "+f"(d3)
                 : "r"(a0), "r"(a1), "r"(a2), "r"(a3), "r"(b0), "r"(b1));
}

__global__ void __launch_bounds__(256, 2)
mma_gemm_kernel() {
    __shared__ __align__(16) __nv_bfloat16 As[2][128][PAD];
    __shared__ __align__(16) __nv_bfloat16 Bs[2][128][PAD];

    const int tid = threadIdx.x;
    const int wid = tid >> 5;
    const int lane = tid & 31;
    const int warp_m = wid & 1;
    const int warp_n = wid >> 1;

    const int rowBase = blockIdx.y * 128;
    const int colBase = blockIdx.x * 128;

    const __nv_bfloat16* Ab = g_xb  + (size_t)rowBase * DDIM;
    const __nv_bfloat16* Bb = g_cbb + (size_t)colBase * DDIM;

    const int ldr0 = tid >> 1;
    const int ldc0 = (tid & 1) * 2;

    float acc[4][4][4];
    #pragma unroll
    for (int mt = 0; mt < 4; ++mt)
        #pragma unroll
        for (int nt = 0; nt < 4; ++nt)
            #pragma unroll
            for (int r = 0; r < 4; ++r) acc[mt][nt][r] = 0.f;

    const int a_row = warp_m * 64 + (lane & 15);
    const int a_koff = (lane >> 4) << 3;
    const int b_row = warp_n * 32 + (lane & 7);
    const int b_koff = ((lane >> 3) & 1) << 3;

    auto load_stage = [&](int buf, int kt) {
        #pragma unroll
        for (int s = 0; s < 2; ++s) {
            int chunk = ldc0 + s;
            cp_async16(smem_u32(&As[buf][ldr0][chunk * 8]),
                       Ab + (size_t)ldr0 * DDIM + kt + chunk * 8);
            cp_async16(smem_u32(&Bs[buf][ldr0][chunk * 8]),
                       Bb + (size_t)ldr0 * DDIM + kt + chunk * 8);
        }
    };

    load_stage(0, 0);
    cp_commit();

    const int NCHUNK = DDIM / BKC;   // 16
    for (int kc = 0; kc < NCHUNK; ++kc) {
        const int buf = kc & 1;
        if (kc + 1 < NCHUNK) {
            load_stage(buf ^ 1, (kc + 1) * BKC);
            cp_commit();
            cp_wait<1>();
        } else {
            cp_wait<0>();
        }
        __syncthreads();

        #pragma unroll
        for (int kk = 0; kk < BKC; kk += 16) {
            uint32_t afr[4][4];
            #pragma unroll
            for (int mt = 0; mt < 4; ++mt)
                ldsm_x4(afr[mt][0], afr[mt][1], afr[mt][2], afr[mt][3],
                        smem_u32(&As[buf][a_row + mt * 16][kk + a_koff]));
            uint32_t bfr[4][2];
            #pragma unroll
            for (int nt = 0; nt < 4; ++nt)
                ldsm_x2(bfr[nt][0], bfr[nt][1],
                        smem_u32(&Bs[buf][b_row + nt * 8][kk + b_koff]));
            #pragma unroll
            for (int mt = 0; mt < 4; ++mt)
                #pragma unroll
                for (int nt = 0; nt < 4; ++nt)
                    mma_bf16(acc[mt][nt][0], acc[mt][nt][1],
                             acc[mt][nt][2], acc[mt][nt][3],
                             afr[mt][0], afr[mt][1], afr[mt][2], afr[mt][3],
                             bfr[nt][0], bfr[nt][1]);
        }
        __syncthreads();
    }

    // epilogue: s = 2*acc - c2[col]  (selection scores only)
    #pragma unroll
    for (int nt = 0; nt < 4; ++nt) {
        const int col = colBase + warp_n * 32 + nt * 8 + (lane & 3) * 2;
        const float c2a = g_c2[col], c2b = g_c2[col + 1];
        #pragma unroll
        for (int mt = 0; mt < 4; ++mt) {
            const int row = rowBase + warp_m * 64 + mt * 16 + (lane >> 2);
            float2 v0, v1;
            v0.x = 2.f * acc[mt][nt][0] - c2a;
            v0.y = 2.f * acc[mt][nt][1] - c2b;
            v1.x = 2.f * acc[mt][nt][2] - c2a;
            v1.y = 2.f * acc[mt][nt][3] - c2b;
            *(float2*)(g_scores + (size_t)row * KC + col) = v0;
            *(float2*)(g_scores + (size_t)(row + 8) * KC + col) = v1;
        }
    }
}

// ===========================================================================
// K1: per row, exact 9th-largest approx score -> shortlist to gmem.
// UNCHANGED from the round-12 passing kernel.
// ===========================================================================
__global__ void __launch_bounds__(256, 6)
select_kernel() {
    const int n = blockIdx.x;
    const int tid = threadIdx.x;
    const int wid = tid >> 5;
    const int lane = tid & 31;
    const float* srow = g_scores + (size_t)n * KC;

    __shared__ float wtop[8][9];
    __shared__ float sA9;
    __shared__ int   cnt;

    float v[16];
    #pragma unroll
    for (int i = 0; i < 16; ++i) v[i] = srow[tid + 256 * i];

    float ls[9];
    #pragma unroll
    for (int i = 0; i < 9; ++i) ls[i] = -FLT_MAX;
    #pragma unroll
    for (int i = 0; i < 16; ++i) {
        float val = v[i];
        if (val > ls[8]) {
            ls[8] = val;
            #pragma unroll
            for (int j = 8; j > 0; --j) {
                if (ls[j] > ls[j - 1]) {
                    float tv = ls[j]; ls[j] = ls[j - 1]; ls[j - 1] = tv;
                }
            }
        }
    }

    {
        float cand = ls[0];
        int ptr = 0;
        #pragma unroll
        for (int r = 0; r < 9; ++r) {
            float m = cand;
            #pragma unroll
            for (int off = 16; off > 0; off >>= 1)
                m = fmaxf(m, __shfl_xor_sync(0xffffffffu, m, off));
            unsigned msk = __ballot_sync(0xffffffffu, cand == m);
            if (lane == (__ffs(msk) - 1)) {
                ++ptr;
                cand = (ptr < 9) ? ls[ptr] : -FLT_MAX;
            }
            if (lane == 0) wtop[wid][r] = m;
        }
    }
    __syncthreads();

    if (wid == 0) {
        float cand = (lane < 8) ? wtop[lane][0] : -FLT_MAX;
        int ptr = 0;
        float m = -FLT_MAX;
        #pragma unroll
        for (int r = 0; r < 9; ++r) {
            m = cand;
            #pragma unroll
            for (int off = 16; off > 0; off >>= 1)
                m = fmaxf(m, __shfl_xor_sync(0xffffffffu, m, off));
            unsigned msk = __ballot_sync(0xffffffffu, cand == m);
            if (lane == (__ffs(msk) - 1)) {
                ++ptr;
                cand = (ptr < 9 && lane < 8) ? wtop[lane][ptr] : -FLT_MAX;
            }
        }
        if (lane == 0) sA9 = m;
    }
    if (tid == 0) cnt = 0;
    __syncthreads();

    {
        const float thresh = sA9 - MARGIN;
        int* slist = g_slist + (size_t)n * SHORTCAP;
        #pragma unroll
        for (int i = 0; i < 16; ++i) {
            if (v[i] >= thresh) {
                int pos = atomicAdd(&cnt, 1);
                if (pos < SHORTCAP) slist[pos] = tid + 256 * i;
            }
        }
    }
    __syncthreads();
    if (tid == 0) g_scnt[n] = (cnt < SHORTCAP) ? cnt : SHORTCAP;
}

// ---------------------------------------------------------------------------
// Tie-probability simulation (R5-identical arithmetic). __noinline__ keeps
// its fp64 register pressure out of the finalize hot path.
// ---------------------------------------------------------------------------
__device__ __noinline__ float tie_prob(float a2, float s8, float s9,
                                       int i8, int i9,
                                       float c2_8, float c2_9) {
    double twoab8 = (double)s8 + (double)c2_8;
    double twoab9 = (double)s9 + (double)c2_9;
    const double ja[5] = {-8e-6, -4e-6, 0.0, 4e-6, 8e-6};
    const int    wa[5] = {1, 4, 6, 4, 1};
    const double jb[3] = {-1.5e-6, 0.0, 1.5e-6};
    const int    wb[3] = {1, 2, 1};
    long long keep = 0, tot = 0;
    for (int p8 = 0; p8 < 5; ++p8)
    for (int p9 = 0; p9 < 5; ++p9)
    for (int q8 = 0; q8 < 3; ++q8)
    for (int q9 = 0; q9 < 3; ++q9) {
        float t8 = (float)(twoab8 + ja[p8]);
        float t9 = (float)(twoab9 + ja[p9]);
        float b8 = (float)((double)c2_8 + jb[q8]);
        float b9 = (float)((double)c2_9 + jb[q9]);
        float u8 = __fsub_rn(a2, t8);
        float u9 = __fsub_rn(a2, t9);
        float d8 = __fadd_rn(u8, b8);
        float d9 = __fadd_rn(u9, b9);
        int wgt = wa[p8] * wa[p9] * wb[q8] * wb[q9];
        tot += wgt;
        if (d8 < d9 || (d8 == d9 && i8 < i9)) keep += wgt;
    }
    return (float)keep / (float)tot;
}

// ===========================================================================
// K2: per row, R5-exact fp32 rescore of the shortlist, byte-identical a2
// tree, warp-parallel exact top-9 (same (value,index) ordering => identical
// picks), tie-sim + softmax, quantize + per-row squared error.
// ===========================================================================
__global__ void __launch_bounds__(256, 6)
finalize_kernel(const float* __restrict__ x, const float* __restrict__ cb,
                float* __restrict__ out) {
    const int n = blockIdx.x;
    const int tid = threadIdx.x;
    const int wid = tid >> 5;
    const int lane = tid & 31;

    __shared__ float xs[DDIM];
    __shared__ float rv[256];
    __shared__ int   listk[SHORTCAP];
    __shared__ float listsF[SHORTCAP];
    __shared__ float tops[9];
    __shared__ int   topi[9];
    __shared__ float w[9];

    // stage x row + own a2 partial (uses only this thread's writes: no barrier)
    const float* xrow = x + (size_t)n * DDIM;
    const float xa = xrow[tid];
    const float xb = xrow[tid + 256];
    xs[tid] = xa;
    xs[tid + 256] = xb;
    {   // BYTE-IDENTICAL partial: d=tid then d=tid+256, fmaf chain from 0
        float s2 = 0.f;
        s2 = fmaf(xa, xa, s2);
        s2 = fmaf(xb, xb, s2);
        rv[tid] = s2;
    }

    const int L = g_scnt[n];
    if (tid < L) listk[tid] = g_slist[(size_t)n * SHORTCAP + tid];
    __syncthreads();

    // R5-exact fp32 rescore: sequential fmaf over d ascending
    if (tid < L) {
        const float4* crow = (const float4*)(cb + (size_t)listk[tid] * DDIM);
        float acc = 0.f;
        #pragma unroll 8
        for (int q = 0; q < DDIM / 4; ++q) {
            float4 c = crow[q];
            acc = fmaf(xs[4 * q + 0], c.x, acc);
            acc = fmaf(xs[4 * q + 1], c.y, acc);
            acc = fmaf(xs[4 * q + 2], c.z, acc);
            acc = fmaf(xs[4 * q + 3], c.w, acc);
        }
        listsF[tid] = 2.f * acc - g_c2[listk[tid]];
    }
    __syncthreads();

    // a2 tree (BYTE-IDENTICAL to all passing rounds: feeds the tie-sim)
    for (int st = 128; st > 0; st >>= 1) {
        if (tid < st) rv[tid] += rv[tid + st];
        __syncthreads();
    }

    // exact top-9 among shortlist (value desc, index asc)
    if (L <= 32) {
        // warp-parallel: unique (value,index) pairs => identical picks
        if (wid == 0) {
            float mv = (lane < L) ? listsF[lane] : -FLT_MAX;
            int   mi = (lane < L) ? listk[lane] : 0x7fffffff;
            #pragma unroll
            for (int r = 0; r < 9; ++r) {
                float bv = mv; int bi = mi;
                #pragma unroll
                for (int off = 16; off > 0; off >>= 1) {
                    float ov = __shfl_xor_sync(0xffffffffu, bv, off);
                    int   oi = __shfl_xor_sync(0xffffffffu, bi, off);
                    if (ov > bv || (ov == bv && oi < bi)) { bv = ov; bi = oi; }
                }
                if (lane == 0) { tops[r] = bv; topi[r] = bi; }
                if (mv == bv && mi == bi) { mv = -FLT_MAX; mi = 0x7fffffff; }
            }
        }
    } else if (tid == 0) {
        // serial fallback (rare): same ordering
        unsigned char usedl[SHORTCAP];
        for (int j = 0; j < L; ++j) usedl[j] = 0;
        for (int it = 0; it < 9; ++it) {
            float bs = -FLT_MAX; int bk = 0x7fffffff; int bj = 0;
            for (int j = 0; j < L; ++j) {
                if (usedl[j]) continue;
                float sv = listsF[j]; int kk = listk[j];
                if (sv > bs || (sv == bs && kk < bk)) { bs = sv; bk = kk; bj = j; }
            }
            usedl[bj] = 1;
            tops[it] = bs;
            topi[it] = bk;
        }
    }
    __syncthreads();

    if (tid == 0) {
        float a2 = rv[0];
        float s8 = tops[7], s9 = tops[8];
        int   i8 = topi[7], i9 = topi[8];
        float g  = s8 - s9;
        float Gf = nextafterf(a2, FLT_MAX) - a2;

        float p = (g >= 3.f * Gf)
                    ? 1.f
                    : tie_prob(a2, s8, s9, i8, i9, g_c2[i8], g_c2[i9]);

        float s0 = tops[0];
        float e[9];
        #pragma unroll
        for (int i = 0; i < 9; ++i) e[i] = expf(tops[i] - s0);
        float sumA = 0.f;
        #pragma unroll
        for (int i = 0; i < 8; ++i) sumA += e[i];
        float sumB = sumA - e[7] + e[8];

        float invA = p / sumA;
        float invB = (1.f - p) / sumB;
        #pragma unroll
        for (int i = 0; i < 7; ++i) w[i] = e[i] * (invA + invB);
        w[7] = e[7] * invA;
        w[8] = e[8] * invB;
    }
    __syncthreads();

    float lw[9]; int idxs[9];
    #pragma unroll
    for (int i = 0; i < 9; ++i) { lw[i] = w[i]; idxs[i] = topi[i]; }

    float err = 0.f;
    #pragma unroll
    for (int d = tid; d < DDIM; d += 256) {
        float q = 0.f;
        #pragma unroll
        for (int i = 0; i < 9; ++i)
            q = fmaf(lw[i], cb[(size_t)idxs[i] * DDIM + d], q);
        out[(size_t)n * DDIM + d] = q;
        float dx = q - xs[d];
        err = fmaf(dx, dx, err);
    }
    rv[tid] = err;
    __syncthreads();
    for (int st = 128; st > 0; st >>= 1) {
        if (tid < st) rv[tid] += rv[tid + st];
        __syncthreads();
    }
    if (tid == 0) g_rowerr[n] = rv[0];
}

// ---------------------------------------------------------------------------
// loss = 1.25 * mean((q-x)^2)
// ---------------------------------------------------------------------------
__global__ void loss_kernel(float* __restrict__ out, int out_size) {
    __shared__ float sm[256];
    float s = 0.f;
    for (int i = threadIdx.x; i < N_ROWS; i += 256) s += g_rowerr[i];
    sm[threadIdx.x] = s;
    __syncthreads();
    for (int st = 128; st > 0; st >>= 1) {
        if (threadIdx.x < st) sm[threadIdx.x] += sm[threadIdx.x + st];
        __syncthreads();
    }
    const int qelems = N_ROWS * DDIM;  // 8388608
    if (threadIdx.x == 0 && out_size > qelems) {
        out[qelems] = 1.25f * sm[0] / (float)qelems;
    }
}

// ---------------------------------------------------------------------------
extern "C" void kernel_launch(void* const* d_in, const int* in_sizes, int n_in,
                              void* d_out, int out_size) {
    const float* x  = (const float*)d_in[0];   // [8,2048,512] f32
    const float* cb = (const float*)d_in[1];   // [4096,512]   f32
    float* out = (float*)d_out;

    conv_kernel<<<(N_ROWS * DDIM + 255) / 256, 256>>>(x, cb);
    c2_kernel<<<KC, 128>>>(cb);

    dim3 grid(KC / 128, N_ROWS / 128);   // 32 n-tiles x 128 m-tiles
    mma_gemm_kernel<<<grid, 256>>>();

    select_kernel<<<N_ROWS, 256>>>();
    finalize_kernel<<<N_ROWS, 256>>>(x, cb, out);

    loss_kernel<<<1, 256>>>(out, out_size);
}

// round 14
// speedup vs baseline: 1.4287x; 1.4287x over previous
#include <cuda_runtime.h>
#include <cuda_bf16.h>
#include <math.h>
#include <float.h>
#include <stdint.h>

// Problem constants (shapes fixed by the dataset)
#define N_ROWS 16384   // B*T = 8*2048
#define DDIM   512
#define KC     4096

// Scratch (device globals -- no allocation allowed)
__device__ float g_scores[(size_t)N_ROWS * KC];   // 256 MB (approx scores)
__device__ float g_c2[KC];
__device__ float g_rowerr[N_ROWS];
__device__ __nv_bfloat16 g_xb[(size_t)N_ROWS * DDIM];   // 16 MB
__device__ __nv_bfloat16 g_cbb[(size_t)KC * DDIM];      // 4 MB

#define SHORTCAP 160
#define MARGIN   0.5f

__device__ int   g_scnt[N_ROWS];                       // shortlist sizes
__device__ int   g_slist[(size_t)N_ROWS * SHORTCAP];   // shortlist indices

// ===========================================================================
// fp32 -> bf16 conversion for x and codebook
// ===========================================================================
__global__ void conv_kernel(const float* __restrict__ x, const float* __restrict__ cb) {
    size_t i = (size_t)blockIdx.x * blockDim.x + threadIdx.x;
    if (i < (size_t)N_ROWS * DDIM) g_xb[i]  = __float2bfloat16(x[i]);
    if (i < (size_t)KC * DDIM)     g_cbb[i] = __float2bfloat16(cb[i]);
}

// ---------------------------------------------------------------------------
// ||c_k||^2  (f32, for epilogue + rescore + tie simulation) -- R5-identical
// ---------------------------------------------------------------------------
__global__ void c2_kernel(const float* __restrict__ cb) {
    int k = blockIdx.x;
    const float* row = cb + (size_t)k * DDIM;
    float s = 0.f;
    for (int d = threadIdx.x; d < DDIM; d += 128) {
        float v = row[d];
        s += v * v;
    }
    __shared__ float sm[128];
    sm[threadIdx.x] = s;
    __syncthreads();
    for (int st = 64; st > 0; st >>= 1) {
        if (threadIdx.x < st) sm[threadIdx.x] += sm[threadIdx.x + st];
        __syncthreads();
    }
    if (threadIdx.x == 0) g_c2[k] = sm[0];
}

// ===========================================================================
// bf16 mma.sync GEMM (baseline-PTX HMMA; tcgen05 unavailable via compute_103).
// SELECTION ONLY: approx S[n,k] = 2*dot_bf16(x_n, c_k) - c2[k]
// REVERTED to the round-12 passing configuration (launch_bounds(256,1):
// no register cap -- (256,2) forced spills and regressed round 13).
// ===========================================================================
#define BKC 32
#define PAD 40

__device__ __forceinline__ uint32_t smem_u32(const void* p) {
    uint32_t a;
    asm("{ .reg .u64 t; cvta.to.shared.u64 t, %1; cvt.u32.u64 %0, t; }"
        : "=r"(a) : "l"(p));
    return a;
}
__device__ __forceinline__ void cp_async16(uint32_t dst, const void* src) {
    asm volatile("cp.async.cg.shared.global [%0], [%1], 16;"
                 :: "r"(dst), "l"(src));
}
__device__ __forceinline__ void cp_commit() {
    asm volatile("cp.async.commit_group;");
}
template <int N>
__device__ __forceinline__ void cp_wait() {
    asm volatile("cp.async.wait_group %0;" :: "n"(N));
}
__device__ __forceinline__ void ldsm_x4(uint32_t& a0, uint32_t& a1,
                                        uint32_t& a2, uint32_t& a3, uint32_t addr) {
    asm volatile("ldmatrix.sync.aligned.m8n8.x4.shared.b16 {%0,%1,%2,%3}, [%4];"
                 : "=r"(a0), "=r"(a1), "=r"(a2), "=r"(a3) : "r"(addr));
}
__device__ __forceinline__ void ldsm_x2(uint32_t& b0, uint32_t& b1, uint32_t addr) {
    asm volatile("ldmatrix.sync.aligned.m8n8.x2.shared.b16 {%0,%1}, [%2];"
                 : "=r"(b0), "=r"(b1) : "r"(addr));
}
__device__ __forceinline__ void mma_bf16(float& d0, float& d1, float& d2, float& d3,
                                         uint32_t a0, uint32_t a1, uint32_t a2, uint32_t a3,
                                         uint32_t b0, uint32_t b1) {
    asm volatile("mma.sync.aligned.m16n8k16.row.col.f32.bf16.bf16.f32 "
                 "{%0,%1,%2,%3}, {%4,%5,%6,%7}, {%8,%9}, {%0,%1,%2,%3};"
                 : "+f"(d0), "+f"(d1), "+f"(d2), "+f"(d3)
                 : "r"(a0), "r"(a1), "r"(a2), "r"(a3), "r"(b0), "r"(b1));
}

__global__ void __launch_bounds__(256, 1)
mma_gemm_kernel() {
    __shared__ __align__(16) __nv_bfloat16 As[2][128][PAD];
    __shared__ __align__(16) __nv_bfloat16 Bs[2][128][PAD];

    const int tid = threadIdx.x;
    const int wid = tid >> 5;
    const int lane = tid & 31;
    const int warp_m = wid & 1;
    const int warp_n = wid >> 1;

    const int rowBase = blockIdx.y * 128;
    const int colBase = blockIdx.x * 128;

    const __nv_bfloat16* Ab = g_xb  + (size_t)rowBase * DDIM;
    const __nv_bfloat16* Bb = g_cbb + (size_t)colBase * DDIM;

    const int ldr0 = tid >> 1;
    const int ldc0 = (tid & 1) * 2;

    float acc[4][4][4];
    #pragma unroll
    for (int mt = 0; mt < 4; ++mt)
        #pragma unroll
        for (int nt = 0; nt < 4; ++nt)
            #pragma unroll
            for (int r = 0; r < 4; ++r) acc[mt][nt][r] = 0.f;

    const int a_row = warp_m * 64 + (lane & 15);
    const int a_koff = (lane >> 4) << 3;
    const int b_row = warp_n * 32 + (lane & 7);
    const int b_koff = ((lane >> 3) & 1) << 3;

    auto load_stage = [&](int buf, int kt) {
        #pragma unroll
        for (int s = 0; s < 2; ++s) {
            int chunk = ldc0 + s;
            cp_async16(smem_u32(&As[buf][ldr0][chunk * 8]),
                       Ab + (size_t)ldr0 * DDIM + kt + chunk * 8);
            cp_async16(smem_u32(&Bs[buf][ldr0][chunk * 8]),
                       Bb + (size_t)ldr0 * DDIM + kt + chunk * 8);
        }
    };

    load_stage(0, 0);
    cp_commit();

    const int NCHUNK = DDIM / BKC;   // 16
    for (int kc = 0; kc < NCHUNK; ++kc) {
        const int buf = kc & 1;
        if (kc + 1 < NCHUNK) {
            load_stage(buf ^ 1, (kc + 1) * BKC);
            cp_commit();
            cp_wait<1>();
        } else {
            cp_wait<0>();
        }
        __syncthreads();

        #pragma unroll
        for (int kk = 0; kk < BKC; kk += 16) {
            uint32_t afr[4][4];
            #pragma unroll
            for (int mt = 0; mt < 4; ++mt)
                ldsm_x4(afr[mt][0], afr[mt][1], afr[mt][2], afr[mt][3],
                        smem_u32(&As[buf][a_row + mt * 16][kk + a_koff]));
            uint32_t bfr[4][2];
            #pragma unroll
            for (int nt = 0; nt < 4; ++nt)
                ldsm_x2(bfr[nt][0], bfr[nt][1],
                        smem_u32(&Bs[buf][b_row + nt * 8][kk + b_koff]));
            #pragma unroll
            for (int mt = 0; mt < 4; ++mt)
                #pragma unroll
                for (int nt = 0; nt < 4; ++nt)
                    mma_bf16(acc[mt][nt][0], acc[mt][nt][1],
                             acc[mt][nt][2], acc[mt][nt][3],
                             afr[mt][0], afr[mt][1], afr[mt][2], afr[mt][3],
                             bfr[nt][0], bfr[nt][1]);
        }
        __syncthreads();
    }

    // epilogue: s = 2*acc - c2[col]  (selection scores only)
    #pragma unroll
    for (int nt = 0; nt < 4; ++nt) {
        const int col = colBase + warp_n * 32 + nt * 8 + (lane & 3) * 2;
        const float c2a = g_c2[col], c2b = g_c2[col + 1];
        #pragma unroll
        for (int mt = 0; mt < 4; ++mt) {
            const int row = rowBase + warp_m * 64 + mt * 16 + (lane >> 2);
            float2 v0, v1;
            v0.x = 2.f * acc[mt][nt][0] - c2a;
            v0.y = 2.f * acc[mt][nt][1] - c2b;
            v1.x = 2.f * acc[mt][nt][2] - c2a;
            v1.y = 2.f * acc[mt][nt][3] - c2b;
            *(float2*)(g_scores + (size_t)row * KC + col) = v0;
            *(float2*)(g_scores + (size_t)(row + 8) * KC + col) = v1;
        }
    }
}

// ===========================================================================
// K1: per row, exact 9th-largest approx score -> shortlist to gmem.
// UNCHANGED from the round-12 passing kernel.
// ===========================================================================
__global__ void __launch_bounds__(256, 6)
select_kernel() {
    const int n = blockIdx.x;
    const int tid = threadIdx.x;
    const int wid = tid >> 5;
    const int lane = tid & 31;
    const float* srow = g_scores + (size_t)n * KC;

    __shared__ float wtop[8][9];
    __shared__ float sA9;
    __shared__ int   cnt;

    float v[16];
    #pragma unroll
    for (int i = 0; i < 16; ++i) v[i] = srow[tid + 256 * i];

    float ls[9];
    #pragma unroll
    for (int i = 0; i < 9; ++i) ls[i] = -FLT_MAX;
    #pragma unroll
    for (int i = 0; i < 16; ++i) {
        float val = v[i];
        if (val > ls[8]) {
            ls[8] = val;
            #pragma unroll
            for (int j = 8; j > 0; --j) {
                if (ls[j] > ls[j - 1]) {
                    float tv = ls[j]; ls[j] = ls[j - 1]; ls[j - 1] = tv;
                }
            }
        }
    }

    {
        float cand = ls[0];
        int ptr = 0;
        #pragma unroll
        for (int r = 0; r < 9; ++r) {
            float m = cand;
            #pragma unroll
            for (int off = 16; off > 0; off >>= 1)
                m = fmaxf(m, __shfl_xor_sync(0xffffffffu, m, off));
            unsigned msk = __ballot_sync(0xffffffffu, cand == m);
            if (lane == (__ffs(msk) - 1)) {
                ++ptr;
                cand = (ptr < 9) ? ls[ptr] : -FLT_MAX;
            }
            if (lane == 0) wtop[wid][r] = m;
        }
    }
    __syncthreads();

    if (wid == 0) {
        float cand = (lane < 8) ? wtop[lane][0] : -FLT_MAX;
        int ptr = 0;
        float m = -FLT_MAX;
        #pragma unroll
        for (int r = 0; r < 9; ++r) {
            m = cand;
            #pragma unroll
            for (int off = 16; off > 0; off >>= 1)
                m = fmaxf(m, __shfl_xor_sync(0xffffffffu, m, off));
            unsigned msk = __ballot_sync(0xffffffffu, cand == m);
            if (lane == (__ffs(msk) - 1)) {
                ++ptr;
                cand = (ptr < 9 && lane < 8) ? wtop[lane][ptr] : -FLT_MAX;
            }
        }
        if (lane == 0) sA9 = m;
    }
    if (tid == 0) cnt = 0;
    __syncthreads();

    {
        const float thresh = sA9 - MARGIN;
        int* slist = g_slist + (size_t)n * SHORTCAP;
        #pragma unroll
        for (int i = 0; i < 16; ++i) {
            if (v[i] >= thresh) {
                int pos = atomicAdd(&cnt, 1);
                if (pos < SHORTCAP) slist[pos] = tid + 256 * i;
            }
        }
    }
    __syncthreads();
    if (tid == 0) g_scnt[n] = (cnt < SHORTCAP) ? cnt : SHORTCAP;
}

// ---------------------------------------------------------------------------
// Tie-probability simulation (R5-identical arithmetic). __noinline__ keeps
// its fp64 register pressure out of the finalize hot path.
// ---------------------------------------------------------------------------
__device__ __noinline__ float tie_prob(float a2, float s8, float s9,
                                       int i8, int i9,
                                       float c2_8, float c2_9) {
    double twoab8 = (double)s8 + (double)c2_8;
    double twoab9 = (double)s9 + (double)c2_9;
    const double ja[5] = {-8e-6, -4e-6, 0.0, 4e-6, 8e-6};
    const int    wa[5] = {1, 4, 6, 4, 1};
    const double jb[3] = {-1.5e-6, 0.0, 1.5e-6};
    const int    wb[3] = {1, 2, 1};
    long long keep = 0, tot = 0;
    for (int p8 = 0; p8 < 5; ++p8)
    for (int p9 = 0; p9 < 5; ++p9)
    for (int q8 = 0; q8 < 3; ++q8)
    for (int q9 = 0; q9 < 3; ++q9) {
        float t8 = (float)(twoab8 + ja[p8]);
        float t9 = (float)(twoab9 + ja[p9]);
        float b8 = (float)((double)c2_8 + jb[q8]);
        float b9 = (float)((double)c2_9 + jb[q9]);
        float u8 = __fsub_rn(a2, t8);
        float u9 = __fsub_rn(a2, t9);
        float d8 = __fadd_rn(u8, b8);
        float d9 = __fadd_rn(u9, b9);
        int wgt = wa[p8] * wa[p9] * wb[q8] * wb[q9];
        tot += wgt;
        if (d8 < d9 || (d8 == d9 && i8 < i9)) keep += wgt;
    }
    return (float)keep / (float)tot;
}

// ===========================================================================
// K2: per row, R5-exact fp32 rescore of the shortlist, byte-identical a2
// tree, warp-parallel exact top-9 (same (value,index) ordering => identical
// picks), tie-sim + softmax, quantize + per-row squared error.
// ===========================================================================
__global__ void __launch_bounds__(256, 6)
finalize_kernel(const float* __restrict__ x, const float* __restrict__ cb,
                float* __restrict__ out) {
    const int n = blockIdx.x;
    const int tid = threadIdx.x;
    const int wid = tid >> 5;
    const int lane = tid & 31;

    __shared__ float xs[DDIM];
    __shared__ float rv[256];
    __shared__ int   listk[SHORTCAP];
    __shared__ float listsF[SHORTCAP];
    __shared__ float tops[9];
    __shared__ int   topi[9];
    __shared__ float w[9];

    // stage x row + own a2 partial (uses only this thread's writes: no barrier)
    const float* xrow = x + (size_t)n * DDIM;
    const float xa = xrow[tid];
    const float xb = xrow[tid + 256];
    xs[tid] = xa;
    xs[tid + 256] = xb;
    {   // BYTE-IDENTICAL partial: d=tid then d=tid+256, fmaf chain from 0
        float s2 = 0.f;
        s2 = fmaf(xa, xa, s2);
        s2 = fmaf(xb, xb, s2);
        rv[tid] = s2;
    }

    const int L = g_scnt[n];
    if (tid < L) listk[tid] = g_slist[(size_t)n * SHORTCAP + tid];
    __syncthreads();

    // R5-exact fp32 rescore: sequential fmaf over d ascending
    if (tid < L) {
        const float4* crow = (const float4*)(cb + (size_t)listk[tid] * DDIM);
        float acc = 0.f;
        #pragma unroll 8
        for (int q = 0; q < DDIM / 4; ++q) {
            float4 c = crow[q];
            acc = fmaf(xs[4 * q + 0], c.x, acc);
            acc = fmaf(xs[4 * q + 1], c.y, acc);
            acc = fmaf(xs[4 * q + 2], c.z, acc);
            acc = fmaf(xs[4 * q + 3], c.w, acc);
        }
        listsF[tid] = 2.f * acc - g_c2[listk[tid]];
    }
    __syncthreads();

    // a2 tree (BYTE-IDENTICAL to all passing rounds: feeds the tie-sim)
    for (int st = 128; st > 0; st >>= 1) {
        if (tid < st) rv[tid] += rv[tid + st];
        __syncthreads();
    }

    // exact top-9 among shortlist (value desc, index asc)
    if (L <= 32) {
        // warp-parallel: unique (value,index) pairs => identical picks
        if (wid == 0) {
            float mv = (lane < L) ? listsF[lane] : -FLT_MAX;
            int   mi = (lane < L) ? listk[lane] : 0x7fffffff;
            #pragma unroll
            for (int r = 0; r < 9; ++r) {
                float bv = mv; int bi = mi;
                #pragma unroll
                for (int off = 16; off > 0; off >>= 1) {
                    float ov = __shfl_xor_sync(0xffffffffu, bv, off);
                    int   oi = __shfl_xor_sync(0xffffffffu, bi, off);
                    if (ov > bv || (ov == bv && oi < bi)) { bv = ov; bi = oi; }
                }
                if (lane == 0) { tops[r] = bv; topi[r] = bi; }
                if (mv == bv && mi == bi) { mv = -FLT_MAX; mi = 0x7fffffff; }
            }
        }
    } else if (tid == 0) {
        // serial fallback (rare): same ordering
        unsigned char usedl[SHORTCAP];
        for (int j = 0; j < L; ++j) usedl[j] = 0;
        for (int it = 0; it < 9; ++it) {
            float bs = -FLT_MAX; int bk = 0x7fffffff; int bj = 0;
            for (int j = 0; j < L; ++j) {
                if (usedl[j]) continue;
                float sv = listsF[j]; int kk = listk[j];
                if (sv > bs || (sv == bs && kk < bk)) { bs = sv; bk = kk; bj = j; }
            }
            usedl[bj] = 1;
            tops[it] = bs;
            topi[it] = bk;
        }
    }
    __syncthreads();

    if (tid == 0) {
        float a2 = rv[0];
        float s8 = tops[7], s9 = tops[8];
        int   i8 = topi[7], i9 = topi[8];
        float g  = s8 - s9;
        float Gf = nextafterf(a2, FLT_MAX) - a2;

        float p = (g >= 3.f * Gf)
                    ? 1.f
                    : tie_prob(a2, s8, s9, i8, i9, g_c2[i8], g_c2[i9]);

        float s0 = tops[0];
        float e[9];
        #pragma unroll
        for (int i = 0; i < 9; ++i) e[i] = expf(tops[i] - s0);
        float sumA = 0.f;
        #pragma unroll
        for (int i = 0; i < 8; ++i) sumA += e[i];
        float sumB = sumA - e[7] + e[8];

        float invA = p / sumA;
        float invB = (1.f - p) / sumB;
        #pragma unroll
        for (int i = 0; i < 7; ++i) w[i] = e[i] * (invA + invB);
        w[7] = e[7] * invA;
        w[8] = e[8] * invB;
    }
    __syncthreads();

    float lw[9]; int idxs[9];
    #pragma unroll
    for (int i = 0; i < 9; ++i) { lw[i] = w[i]; idxs[i] = topi[i]; }

    float err = 0.f;
    #pragma unroll
    for (int d = tid; d < DDIM; d += 256) {
        float q = 0.f;
        #pragma unroll
        for (int i = 0; i < 9; ++i)
            q = fmaf(lw[i], cb[(size_t)idxs[i] * DDIM + d], q);
        out[(size_t)n * DDIM + d] = q;
        float dx = q - xs[d];
        err = fmaf(dx, dx, err);
    }
    rv[tid] = err;
    __syncthreads();
    for (int st = 128; st > 0; st >>= 1) {
        if (tid < st) rv[tid] += rv[tid + st];
        __syncthreads();
    }
    if (tid == 0) g_rowerr[n] = rv[0];
}

// ---------------------------------------------------------------------------
// loss = 1.25 * mean((q-x)^2)
// ---------------------------------------------------------------------------
__global__ void loss_kernel(float* __restrict__ out, int out_size) {
    __shared__ float sm[256];
    float s = 0.f;
    for (int i = threadIdx.x; i < N_ROWS; i += 256) s += g_rowerr[i];
    sm[threadIdx.x] = s;
    __syncthreads();
    for (int st = 128; st > 0; st >>= 1) {
        if (threadIdx.x < st) sm[threadIdx.x] += sm[threadIdx.x + st];
        __syncthreads();
    }
    const int qelems = N_ROWS * DDIM;  // 8388608
    if (threadIdx.x == 0 && out_size > qelems) {
        out[qelems] = 1.25f * sm[0] / (float)qelems;
    }
}

// ---------------------------------------------------------------------------
extern "C" void kernel_launch(void* const* d_in, const int* in_sizes, int n_in,
                              void* d_out, int out_size) {
    const float* x  = (const float*)d_in[0];   // [8,2048,512] f32
    const float* cb = (const float*)d_in[1];   // [4096,512]   f32
    float* out = (float*)d_out;

    conv_kernel<<<(N_ROWS * DDIM + 255) / 256, 256>>>(x, cb);
    c2_kernel<<<KC, 128>>>(cb);

    dim3 grid(KC / 128, N_ROWS / 128);   // 32 n-tiles x 128 m-tiles
    mma_gemm_kernel<<<grid, 256>>>();

    select_kernel<<<N_ROWS, 256>>>();
    finalize_kernel<<<N_ROWS, 256>>>(x, cb, out);

    loss_kernel<<<1, 256>>>(out, out_size);
}

// round 15
// speedup vs baseline: 1.5757x; 1.1029x over previous
#include <cuda_runtime.h>
#include <cuda_bf16.h>
#include <math.h>
#include <float.h>
#include <stdint.h>

// Problem constants (shapes fixed by the dataset)
#define N_ROWS 16384   // B*T = 8*2048
#define DDIM   512
#define KC     4096

// Scratch (device globals -- no allocation allowed)
__device__ float g_scores[(size_t)N_ROWS * KC];   // 256 MB (approx scores)
__device__ float g_c2[KC];
__device__ float g_rowerr[N_ROWS];
__device__ __nv_bfloat16 g_xb[(size_t)N_ROWS * DDIM];   // 16 MB
__device__ __nv_bfloat16 g_cbb[(size_t)KC * DDIM];      // 4 MB

#define SHORTCAP 160
#define MARGIN   0.5f

__device__ int   g_scnt[N_ROWS];                       // shortlist sizes
__device__ int   g_slist[(size_t)N_ROWS * SHORTCAP];   // shortlist indices

// ===========================================================================
// fp32 -> bf16 conversion for x and codebook
// ===========================================================================
__global__ void conv_kernel(const float* __restrict__ x, const float* __restrict__ cb) {
    size_t i = (size_t)blockIdx.x * blockDim.x + threadIdx.x;
    if (i < (size_t)N_ROWS * DDIM) g_xb[i]  = __float2bfloat16(x[i]);
    if (i < (size_t)KC * DDIM)     g_cbb[i] = __float2bfloat16(cb[i]);
}

// ---------------------------------------------------------------------------
// ||c_k||^2  (f32, for epilogue + rescore + tie simulation) -- R5-identical
// ---------------------------------------------------------------------------
__global__ void c2_kernel(const float* __restrict__ cb) {
    int k = blockIdx.x;
    const float* row = cb + (size_t)k * DDIM;
    float s = 0.f;
    for (int d = threadIdx.x; d < DDIM; d += 128) {
        float v = row[d];
        s += v * v;
    }
    __shared__ float sm[128];
    sm[threadIdx.x] = s;
    __syncthreads();
    for (int st = 64; st > 0; st >>= 1) {
        if (threadIdx.x < st) sm[threadIdx.x] += sm[threadIdx.x + st];
        __syncthreads();
    }
    if (threadIdx.x == 0) g_c2[k] = sm[0];
}

// ===========================================================================
// bf16 mma.sync GEMM (baseline-PTX HMMA; tcgen05 unavailable via compute_103).
// SELECTION ONLY: approx S[n,k] = 2*dot_bf16(x_n, c_k) - c2[k]
// CTA tile 128(M) x 256(N), 8 warps as 2(M) x 4(N) -> warp tile 64x64.
// 12 ldmatrix / 32 mma per k16 (vs 8/16 at 64x32). Per-element accumulation
// chain unchanged (k ascending, 16/step) => scores bit-identical to R14.
// Dynamic smem (61.4 KB) -- static limit is 48 KB.
// ===========================================================================
#define BKC 32
#define PAD 40

__device__ __forceinline__ uint32_t smem_u32(const void* p) {
    uint32_t a;
    asm("{ .reg .u64 t; cvta.to.shared.u64 t, %1; cvt.u32.u64 %0, t; }"
        : "=r"(a) : "l"(p));
    return a;
}
__device__ __forceinline__ void cp_async16(uint32_t dst, const void* src) {
    asm volatile("cp.async.cg.shared.global [%0], [%1], 16;"
                 :: "r"(dst), "l"(src));
}
__device__ __forceinline__ void cp_commit() {
    asm volatile("cp.async.commit_group;");
}
template <int N>
__device__ __forceinline__ void cp_wait() {
    asm volatile("cp.async.wait_group %0;" :: "n"(N));
}
__device__ __forceinline__ void ldsm_x4(uint32_t& a0, uint32_t& a1,
                                        uint32_t& a2, uint32_t& a3, uint32_t addr) {
    asm volatile("ldmatrix.sync.aligned.m8n8.x4.shared.b16 {%0,%1,%2,%3}, [%4];"
                 : "=r"(a0), "=r"(a1), "=r"(a2), "=r"(a3) : "r"(addr));
}
__device__ __forceinline__ void ldsm_x2(uint32_t& b0, uint32_t& b1, uint32_t addr) {
    asm volatile("ldmatrix.sync.aligned.m8n8.x2.shared.b16 {%0,%1}, [%2];"
                 : "=r"(b0), "=r"(b1) : "r"(addr));
}
__device__ __forceinline__ void mma_bf16(float& d0, float& d1, float& d2, float& d3,
                                         uint32_t a0, uint32_t a1, uint32_t a2, uint32_t a3,
                                         uint32_t b0, uint32_t b1) {
    asm volatile("mma.sync.aligned.m16n8k16.row.col.f32.bf16.bf16.f32 "
                 "{%0,%1,%2,%3}, {%4,%5,%6,%7}, {%8,%9}, {%0,%1,%2,%3};"
                 : "+f"(d0), "+f"(d1), "+f"(d2), "+f"(d3)
                 : "r"(a0), "r"(a1), "r"(a2), "r"(a3), "r"(b0), "r"(b1));
}

#define GEMM_SMEM_BYTES ((2 * 128 * PAD + 2 * 256 * PAD) * 2)   // 61440

__global__ void __launch_bounds__(256)
mma_gemm_kernel() {
    extern __shared__ __align__(16) __nv_bfloat16 smem_dyn[];
    __nv_bfloat16* Asb = smem_dyn;                  // [2][128][PAD]
    __nv_bfloat16* Bsb = smem_dyn + 2 * 128 * PAD;  // [2][256][PAD]

    const int tid = threadIdx.x;
    const int wid = tid >> 5;
    const int lane = tid & 31;
    const int warp_m = wid & 1;       // 0..1 -> 64 rows
    const int warp_n = wid >> 1;      // 0..3 -> 64 cols

    const int rowBase = blockIdx.y * 128;
    const int colBase = blockIdx.x * 256;

    const __nv_bfloat16* Ab = g_xb  + (size_t)rowBase * DDIM;
    const __nv_bfloat16* Bb = g_cbb + (size_t)colBase * DDIM;

    float acc[4][8][4];
    #pragma unroll
    for (int mt = 0; mt < 4; ++mt)
        #pragma unroll
        for (int nt = 0; nt < 8; ++nt)
            #pragma unroll
            for (int r = 0; r < 4; ++r) acc[mt][nt][r] = 0.f;

    const int a_row = warp_m * 64 + (lane & 15);
    const int a_koff = (lane >> 4) << 3;
    const int b_row = warp_n * 64 + (lane & 7);
    const int b_koff = ((lane >> 3) & 1) << 3;

    // stage loader: 384 rows x 4 chunks of 16B = 1536 cp.async, 6 per thread
    auto load_stage = [&](int buf, int kt) {
        #pragma unroll
        for (int s = 0; s < 6; ++s) {
            const int i = tid + s * 256;
            const int row = i >> 2;          // 0..383
            const int chunk = i & 3;         // 16B chunk within 64B k-slab
            if (row < 128) {
                cp_async16(smem_u32(Asb + (buf * 128 + row) * PAD + chunk * 8),
                           Ab + (size_t)row * DDIM + kt + chunk * 8);
            } else {
                const int br = row - 128;
                cp_async16(smem_u32(Bsb + (buf * 256 + br) * PAD + chunk * 8),
                           Bb + (size_t)br * DDIM + kt + chunk * 8);
            }
        }
    };

    load_stage(0, 0);
    cp_commit();

    const int NCHUNK = DDIM / BKC;   // 16
    for (int kc = 0; kc < NCHUNK; ++kc) {
        const int buf = kc & 1;
        if (kc + 1 < NCHUNK) {
            load_stage(buf ^ 1, (kc + 1) * BKC);
            cp_commit();
            cp_wait<1>();
        } else {
            cp_wait<0>();
        }
        __syncthreads();

        #pragma unroll
        for (int kk = 0; kk < BKC; kk += 16) {
            uint32_t afr[4][4];
            #pragma unroll
            for (int mt = 0; mt < 4; ++mt)
                ldsm_x4(afr[mt][0], afr[mt][1], afr[mt][2], afr[mt][3],
                        smem_u32(Asb + (buf * 128 + a_row + mt * 16) * PAD
                                 + kk + a_koff));
            uint32_t bfr[8][2];
            #pragma unroll
            for (int nt = 0; nt < 8; ++nt)
                ldsm_x2(bfr[nt][0], bfr[nt][1],
                        smem_u32(Bsb + (buf * 256 + b_row + nt * 8) * PAD
                                 + kk + b_koff));
            #pragma unroll
            for (int mt = 0; mt < 4; ++mt)
                #pragma unroll
                for (int nt = 0; nt < 8; ++nt)
                    mma_bf16(acc[mt][nt][0], acc[mt][nt][1],
                             acc[mt][nt][2], acc[mt][nt][3],
                             afr[mt][0], afr[mt][1], afr[mt][2], afr[mt][3],
                             bfr[nt][0], bfr[nt][1]);
        }
        __syncthreads();
    }

    // epilogue: s = 2*acc - c2[col]  (selection scores only)
    #pragma unroll
    for (int nt = 0; nt < 8; ++nt) {
        const int col = colBase + warp_n * 64 + nt * 8 + (lane & 3) * 2;
        const float c2a = g_c2[col], c2b = g_c2[col + 1];
        #pragma unroll
        for (int mt = 0; mt < 4; ++mt) {
            const int row = rowBase + warp_m * 64 + mt * 16 + (lane >> 2);
            float2 v0, v1;
            v0.x = 2.f * acc[mt][nt][0] - c2a;
            v0.y = 2.f * acc[mt][nt][1] - c2b;
            v1.x = 2.f * acc[mt][nt][2] - c2a;
            v1.y = 2.f * acc[mt][nt][3] - c2b;
            *(float2*)(g_scores + (size_t)row * KC + col) = v0;
            *(float2*)(g_scores + (size_t)(row + 8) * KC + col) = v1;
        }
    }
}

// ===========================================================================
// K1: per row, exact 9th-largest approx score -> shortlist to gmem.
// UNCHANGED from the round-14 passing kernel.
// ===========================================================================
__global__ void __launch_bounds__(256, 6)
select_kernel() {
    const int n = blockIdx.x;
    const int tid = threadIdx.x;
    const int wid = tid >> 5;
    const int lane = tid & 31;
    const float* srow = g_scores + (size_t)n * KC;

    __shared__ float wtop[8][9];
    __shared__ float sA9;
    __shared__ int   cnt;

    float v[16];
    #pragma unroll
    for (int i = 0; i < 16; ++i) v[i] = srow[tid + 256 * i];

    float ls[9];
    #pragma unroll
    for (int i = 0; i < 9; ++i) ls[i] = -FLT_MAX;
    #pragma unroll
    for (int i = 0; i < 16; ++i) {
        float val = v[i];
        if (val > ls[8]) {
            ls[8] = val;
            #pragma unroll
            for (int j = 8; j > 0; --j) {
                if (ls[j] > ls[j - 1]) {
                    float tv = ls[j]; ls[j] = ls[j - 1]; ls[j - 1] = tv;
                }
            }
        }
    }

    {
        float cand = ls[0];
        int ptr = 0;
        #pragma unroll
        for (int r = 0; r < 9; ++r) {
            float m = cand;
            #pragma unroll
            for (int off = 16; off > 0; off >>= 1)
                m = fmaxf(m, __shfl_xor_sync(0xffffffffu, m, off));
            unsigned msk = __ballot_sync(0xffffffffu, cand == m);
            if (lane == (__ffs(msk) - 1)) {
                ++ptr;
                cand = (ptr < 9) ? ls[ptr] : -FLT_MAX;
            }
            if (lane == 0) wtop[wid][r] = m;
        }
    }
    __syncthreads();

    if (wid == 0) {
        float cand = (lane < 8) ? wtop[lane][0] : -FLT_MAX;
        int ptr = 0;
        float m = -FLT_MAX;
        #pragma unroll
        for (int r = 0; r < 9; ++r) {
            m = cand;
            #pragma unroll
            for (int off = 16; off > 0; off >>= 1)
                m = fmaxf(m, __shfl_xor_sync(0xffffffffu, m, off));
            unsigned msk = __ballot_sync(0xffffffffu, cand == m);
            if (lane == (__ffs(msk) - 1)) {
                ++ptr;
                cand = (ptr < 9 && lane < 8) ? wtop[lane][ptr] : -FLT_MAX;
            }
        }
        if (lane == 0) sA9 = m;
    }
    if (tid == 0) cnt = 0;
    __syncthreads();

    {
        const float thresh = sA9 - MARGIN;
        int* slist = g_slist + (size_t)n * SHORTCAP;
        #pragma unroll
        for (int i = 0; i < 16; ++i) {
            if (v[i] >= thresh) {
                int pos = atomicAdd(&cnt, 1);
                if (pos < SHORTCAP) slist[pos] = tid + 256 * i;
            }
        }
    }
    __syncthreads();
    if (tid == 0) g_scnt[n] = (cnt < SHORTCAP) ? cnt : SHORTCAP;
}

// ---------------------------------------------------------------------------
// Tie-probability simulation (R5-identical arithmetic). __noinline__ keeps
// its fp64 register pressure out of the finalize hot path.
// ---------------------------------------------------------------------------
__device__ __noinline__ float tie_prob(float a2, float s8, float s9,
                                       int i8, int i9,
                                       float c2_8, float c2_9) {
    double twoab8 = (double)s8 + (double)c2_8;
    double twoab9 = (double)s9 + (double)c2_9;
    const double ja[5] = {-8e-6, -4e-6, 0.0, 4e-6, 8e-6};
    const int    wa[5] = {1, 4, 6, 4, 1};
    const double jb[3] = {-1.5e-6, 0.0, 1.5e-6};
    const int    wb[3] = {1, 2, 1};
    long long keep = 0, tot = 0;
    for (int p8 = 0; p8 < 5; ++p8)
    for (int p9 = 0; p9 < 5; ++p9)
    for (int q8 = 0; q8 < 3; ++q8)
    for (int q9 = 0; q9 < 3; ++q9) {
        float t8 = (float)(twoab8 + ja[p8]);
        float t9 = (float)(twoab9 + ja[p9]);
        float b8 = (float)((double)c2_8 + jb[q8]);
        float b9 = (float)((double)c2_9 + jb[q9]);
        float u8 = __fsub_rn(a2, t8);
        float u9 = __fsub_rn(a2, t9);
        float d8 = __fadd_rn(u8, b8);
        float d9 = __fadd_rn(u9, b9);
        int wgt = wa[p8] * wa[p9] * wb[q8] * wb[q9];
        tot += wgt;
        if (d8 < d9 || (d8 == d9 && i8 < i9)) keep += wgt;
    }
    return (float)keep / (float)tot;
}

// ===========================================================================
// K2: per row, R5-exact fp32 rescore of the shortlist, byte-identical a2
// tree, warp-parallel exact top-9, tie-sim + softmax, quantize + row error.
// UNCHANGED from the round-14 passing kernel.
// ===========================================================================
__global__ void __launch_bounds__(256, 6)
finalize_kernel(const float* __restrict__ x, const float* __restrict__ cb,
                float* __restrict__ out) {
    const int n = blockIdx.x;
    const int tid = threadIdx.x;
    const int wid = tid >> 5;
    const int lane = tid & 31;

    __shared__ float xs[DDIM];
    __shared__ float rv[256];
    __shared__ int   listk[SHORTCAP];
    __shared__ float listsF[SHORTCAP];
    __shared__ float tops[9];
    __shared__ int   topi[9];
    __shared__ float w[9];

    const float* xrow = x + (size_t)n * DDIM;
    const float xa = xrow[tid];
    const float xb = xrow[tid + 256];
    xs[tid] = xa;
    xs[tid + 256] = xb;
    {
        float s2 = 0.f;
        s2 = fmaf(xa, xa, s2);
        s2 = fmaf(xb, xb, s2);
        rv[tid] = s2;
    }

    const int L = g_scnt[n];
    if (tid < L) listk[tid] = g_slist[(size_t)n * SHORTCAP + tid];
    __syncthreads();

    if (tid < L) {
        const float4* crow = (const float4*)(cb + (size_t)listk[tid] * DDIM);
        float acc = 0.f;
        #pragma unroll 8
        for (int q = 0; q < DDIM / 4; ++q) {
            float4 c = crow[q];
            acc = fmaf(xs[4 * q + 0], c.x, acc);
            acc = fmaf(xs[4 * q + 1], c.y, acc);
            acc = fmaf(xs[4 * q + 2], c.z, acc);
            acc = fmaf(xs[4 * q + 3], c.w, acc);
        }
        listsF[tid] = 2.f * acc - g_c2[listk[tid]];
    }
    __syncthreads();

    for (int st = 128; st > 0; st >>= 1) {
        if (tid < st) rv[tid] += rv[tid + st];
        __syncthreads();
    }

    if (L <= 32) {
        if (wid == 0) {
            float mv = (lane < L) ? listsF[lane] : -FLT_MAX;
            int   mi = (lane < L) ? listk[lane] : 0x7fffffff;
            #pragma unroll
            for (int r = 0; r < 9; ++r) {
                float bv = mv; int bi = mi;
                #pragma unroll
                for (int off = 16; off > 0; off >>= 1) {
                    float ov = __shfl_xor_sync(0xffffffffu, bv, off);
                    int   oi = __shfl_xor_sync(0xffffffffu, bi, off);
                    if (ov > bv || (ov == bv && oi < bi)) { bv = ov; bi = oi; }
                }
                if (lane == 0) { tops[r] = bv; topi[r] = bi; }
                if (mv == bv && mi == bi) { mv = -FLT_MAX; mi = 0x7fffffff; }
            }
        }
    } else if (tid == 0) {
        unsigned char usedl[SHORTCAP];
        for (int j = 0; j < L; ++j) usedl[j] = 0;
        for (int it = 0; it < 9; ++it) {
            float bs = -FLT_MAX; int bk = 0x7fffffff; int bj = 0;
            for (int j = 0; j < L; ++j) {
                if (usedl[j]) continue;
                float sv = listsF[j]; int kk = listk[j];
                if (sv > bs || (sv == bs && kk < bk)) { bs = sv; bk = kk; bj = j; }
            }
            usedl[bj] = 1;
            tops[it] = bs;
            topi[it] = bk;
        }
    }
    __syncthreads();

    if (tid == 0) {
        float a2 = rv[0];
        float s8 = tops[7], s9 = tops[8];
        int   i8 = topi[7], i9 = topi[8];
        float g  = s8 - s9;
        float Gf = nextafterf(a2, FLT_MAX) - a2;

        float p = (g >= 3.f * Gf)
                    ? 1.f
                    : tie_prob(a2, s8, s9, i8, i9, g_c2[i8], g_c2[i9]);

        float s0 = tops[0];
        float e[9];
        #pragma unroll
        for (int i = 0; i < 9; ++i) e[i] = expf(tops[i] - s0);
        float sumA = 0.f;
        #pragma unroll
        for (int i = 0; i < 8; ++i) sumA += e[i];
        float sumB = sumA - e[7] + e[8];

        float invA = p / sumA;
        float invB = (1.f - p) / sumB;
        #pragma unroll
        for (int i = 0; i < 7; ++i) w[i] = e[i] * (invA + invB);
        w[7] = e[7] * invA;
        w[8] = e[8] * invB;
    }
    __syncthreads();

    float lw[9]; int idxs[9];
    #pragma unroll
    for (int i = 0; i < 9; ++i) { lw[i] = w[i]; idxs[i] = topi[i]; }

    float err = 0.f;
    #pragma unroll
    for (int d = tid; d < DDIM; d += 256) {
        float q = 0.f;
        #pragma unroll
        for (int i = 0; i < 9; ++i)
            q = fmaf(lw[i], cb[(size_t)idxs[i] * DDIM + d], q);
        out[(size_t)n * DDIM + d] = q;
        float dx = q - xs[d];
        err = fmaf(dx, dx, err);
    }
    rv[tid] = err;
    __syncthreads();
    for (int st = 128; st > 0; st >>= 1) {
        if (tid < st) rv[tid] += rv[tid + st];
        __syncthreads();
    }
    if (tid == 0) g_rowerr[n] = rv[0];
}

// ---------------------------------------------------------------------------
// loss = 1.25 * mean((q-x)^2)
// ---------------------------------------------------------------------------
__global__ void loss_kernel(float* __restrict__ out, int out_size) {
    __shared__ float sm[256];
    float s = 0.f;
    for (int i = threadIdx.x; i < N_ROWS; i += 256) s += g_rowerr[i];
    sm[threadIdx.x] = s;
    __syncthreads();
    for (int st = 128; st > 0; st >>= 1) {
        if (threadIdx.x < st) sm[threadIdx.x] += sm[threadIdx.x + st];
        __syncthreads();
    }
    const int qelems = N_ROWS * DDIM;  // 8388608
    if (threadIdx.x == 0 && out_size > qelems) {
        out[qelems] = 1.25f * sm[0] / (float)qelems;
    }
}

// ---------------------------------------------------------------------------
extern "C" void kernel_launch(void* const* d_in, const int* in_sizes, int n_in,
                              void* d_out, int out_size) {
    const float* x  = (const float*)d_in[0];   // [8,2048,512] f32
    const float* cb = (const float*)d_in[1];   // [4096,512]   f32
    float* out = (float*)d_out;

    (void)cudaFuncSetAttribute(mma_gemm_kernel,
                               cudaFuncAttributeMaxDynamicSharedMemorySize,
                               GEMM_SMEM_BYTES);

    conv_kernel<<<(N_ROWS * DDIM + 255) / 256, 256>>>(x, cb);
    c2_kernel<<<KC, 128>>>(cb);

    dim3 grid(KC / 256, N_ROWS / 128);   // 16 n-tiles x 128 m-tiles
    mma_gemm_kernel<<<grid, 256, GEMM_SMEM_BYTES>>>();

    select_kernel<<<N_ROWS, 256>>>();
    finalize_kernel<<<N_ROWS, 256>>>(x, cb, out);

    loss_kernel<<<1, 256>>>(out, out_size);
}